// round 14
// baseline (speedup 1.0000x reference)
#include <cuda_runtime.h>
#include <cstdint>

#define N_NODES 100000
#define N_EDGES 1600000
#define N_GRAPHS 256
#define SCAN_BLK 1024   // elements per scan block

typedef unsigned long long u64;

// Scratch (device globals; no allocation allowed). 2-buffer ping-pong.
__device__ __align__(256) float g_buf[2][N_NODES * 64];
__device__ __align__(256) float g_sums[N_GRAPHS * 64];
__device__ __align__(256) float g_cnt[N_GRAPHS];

// CSR scratch: edges grouped by destination node.
__device__ __align__(16) int g_off[N_NODES + 1];  // exclusive degree prefix
__device__ __align__(16) int g_cur[N_NODES];      // counts, then fill cursors
__device__ __align__(16) int g_csr[N_EDGES];      // src ids grouped by dst
__device__ int g_bsum[128];                       // spine of the scan

__device__ __forceinline__ float* bsel(int s) { return g_buf[s]; }

__device__ __forceinline__ void fma2(u64& acc, u64 a, u64 b) {
    asm("fma.rn.f32x2 %0, %1, %2, %0;" : "+l"(acc) : "l"(a), "l"(b));
}

// ---------------------------------------------------------------------------
// Degree histogram over dst. Also zeroes pooling accumulators (consumed by
// k_final of the previous replay; safe to reset here, in-stream).
// g_cur is zero at entry: zero-initialized at load, re-zeroed by k_gemm1.
// ---------------------------------------------------------------------------
__global__ void k_count(const int* __restrict__ ei, int n_edges) {
    int e = blockIdx.x * blockDim.x + threadIdx.x;
    if (e < N_GRAPHS * 64) g_sums[e] = 0.f;
    if (e < N_GRAPHS) g_cnt[e] = 0.f;
    if (e < n_edges) atomicAdd(&g_cur[ei[n_edges + e]], 1);
}

// ---------------------------------------------------------------------------
// Scan pass 1: per-1024-element block exclusive scan of g_cur -> g_off,
// block totals -> g_bsum.
// ---------------------------------------------------------------------------
__global__ __launch_bounds__(256) void k_scan1(int n) {
    __shared__ int tsum[256];
    int t = threadIdx.x;
    int base = blockIdx.x * SCAN_BLK + t * 4;
    int v0 = (base + 0 < n) ? g_cur[base + 0] : 0;
    int v1 = (base + 1 < n) ? g_cur[base + 1] : 0;
    int v2 = (base + 2 < n) ? g_cur[base + 2] : 0;
    int v3 = (base + 3 < n) ? g_cur[base + 3] : 0;
    int s1 = v0 + v1, s2 = s1 + v2, s3 = s2 + v3;
    tsum[t] = s3;
    __syncthreads();
    for (int off = 1; off < 256; off <<= 1) {
        int x = (t >= off) ? tsum[t - off] : 0;
        __syncthreads();
        tsum[t] += x;
        __syncthreads();
    }
    int excl = (t > 0) ? tsum[t - 1] : 0;
    if (t == 255) g_bsum[blockIdx.x] = tsum[255];
    if (base + 0 < n) g_off[base + 0] = excl;
    if (base + 1 < n) g_off[base + 1] = excl + v0;
    if (base + 2 < n) g_off[base + 2] = excl + s1;
    if (base + 3 < n) g_off[base + 3] = excl + s2;
}

// ---------------------------------------------------------------------------
// Scan pass 2 (spine folded in): every block scans the <=128-entry spine
// locally, then applies its prefix. Final offsets -> g_off, cursors -> g_cur.
// ---------------------------------------------------------------------------
__global__ __launch_bounds__(256) void k_scan3(int n, int nblk) {
    __shared__ int sp[128];
    int t = threadIdx.x;
    if (t < 128) sp[t] = (t < nblk) ? g_bsum[t] : 0;
    __syncthreads();
    for (int off = 1; off < 128; off <<= 1) {
        int x = (t < 128 && t >= off) ? sp[t - off] : 0;
        __syncthreads();
        if (t < 128) sp[t] += x;
        __syncthreads();
    }
    int b = blockIdx.x;
    int spine = (b > 0) ? sp[b - 1] : 0;
#pragma unroll
    for (int r = 0; r < 4; r++) {
        int i = b * SCAN_BLK + r * 256 + t;
        if (i < n) {
            int o = g_off[i] + spine;
            g_off[i] = o;
            g_cur[i] = o;
        }
    }
}

// ---------------------------------------------------------------------------
// Fill CSR: group src ids by dst.
// ---------------------------------------------------------------------------
__global__ void k_fill(const int* __restrict__ ei, int n_edges) {
    int e = blockIdx.x * blockDim.x + threadIdx.x;
    if (e < n_edges) {
        int dst = ei[n_edges + e];
        int pos = atomicAdd(&g_cur[dst], 1);
        g_csr[pos] = ei[e];
    }
}

// ---------------------------------------------------------------------------
// Layer-1 GEMM: m = x @ W1 (K=128), f32x2 FFMA2 path.
// 64x64 tile; W staged per 64-K chunk (16KB) + duplicated {h,h} Hs (32KB).
// Also re-zeroes g_cur for the next replay (runs after k_fill).
// ---------------------------------------------------------------------------
__global__ __launch_bounds__(256) void k_gemm1(const float* __restrict__ x,
                                               const float* __restrict__ W,
                                               int msel, int n_nodes) {
    __shared__ float Ws[64 * 64];    // 16KB (one K-chunk)
    __shared__ float2 Hs[64 * 64];   // 32KB, duplicated pairs
    int t = threadIdx.x;
    int base = blockIdx.x * 64;

    if (t < 64 && base + t < n_nodes) g_cur[base + t] = 0;

    int oj = (t & 15) * 4;
    int on = (t >> 4) * 4;
    u64 acc[4][2] = {};

#pragma unroll
    for (int kc = 0; kc < 2; kc++) {
        __syncthreads();
        for (int i = t; i < 64 * 16; i += 256)
            ((float4*)Ws)[i] = ((const float4*)(W + kc * 64 * 64))[i];
        for (int i = t; i < 64 * 16; i += 256) {
            int n = i >> 4, c = i & 15;
            int node = base + n;
            float4 v = make_float4(0.f, 0.f, 0.f, 0.f);
            if (node < n_nodes)
                v = ((const float4*)(x + (size_t)node * 128 + kc * 64))[c];
            float2* hp = &Hs[n * 64 + c * 4];
            hp[0] = make_float2(v.x, v.x);
            hp[1] = make_float2(v.y, v.y);
            hp[2] = make_float2(v.z, v.z);
            hp[3] = make_float2(v.w, v.w);
        }
        __syncthreads();
#pragma unroll 8
        for (int k = 0; k < 64; k++) {
            ulonglong2 w2 = *(const ulonglong2*)&Ws[k * 64 + oj];
#pragma unroll
            for (int i = 0; i < 4; i++) {
                u64 hh = *(const u64*)&Hs[(on + i) * 64 + k];
                fma2(acc[i][0], hh, w2.x);
                fma2(acc[i][1], hh, w2.y);
            }
        }
    }
    float* m = bsel(msel);
#pragma unroll
    for (int i = 0; i < 4; i++) {
        int node = base + on + i;
        if (node < n_nodes) {
            float2 a0 = *(float2*)&acc[i][0];
            float2 a1 = *(float2*)&acc[i][1];
            *(float4*)(m + (size_t)node * 64 + oj) = make_float4(a0.x, a0.y, a1.x, a1.y);
        }
    }
}

// ---------------------------------------------------------------------------
// Layers 2/3 GEMM: m = relu(h_in) @ W (K=64), f32x2 FFMA2 path.
// zero_pool=1 on the layer-3 call re-zeroes nothing (pool zeroed in k_count).
// ---------------------------------------------------------------------------
__global__ __launch_bounds__(256) void k_gemm_relu(int insel, const float* __restrict__ W,
                                                   int msel, int n_nodes) {
    __shared__ float Ws[64 * 64];    // 16KB
    __shared__ float2 Hs[64 * 64];   // 32KB, duplicated pairs
    int t = threadIdx.x;
    const float* src = bsel(insel);
    int base = blockIdx.x * 64;

    for (int i = t; i < 64 * 16; i += 256)
        ((float4*)Ws)[i] = ((const float4*)W)[i];
    for (int i = t; i < 64 * 16; i += 256) {
        int n = i >> 4, c = i & 15;
        int node = base + n;
        float4 v = make_float4(0.f, 0.f, 0.f, 0.f);
        if (node < n_nodes) v = ((const float4*)(src + (size_t)node * 64))[c];
        v.x = fmaxf(v.x, 0.f); v.y = fmaxf(v.y, 0.f);
        v.z = fmaxf(v.z, 0.f); v.w = fmaxf(v.w, 0.f);
        float2* hp = &Hs[n * 64 + c * 4];
        hp[0] = make_float2(v.x, v.x);
        hp[1] = make_float2(v.y, v.y);
        hp[2] = make_float2(v.z, v.z);
        hp[3] = make_float2(v.w, v.w);
    }
    __syncthreads();

    int oj = (t & 15) * 4;
    int on = (t >> 4) * 4;
    u64 acc[4][2] = {};
#pragma unroll 8
    for (int k = 0; k < 64; k++) {
        ulonglong2 w2 = *(const ulonglong2*)&Ws[k * 64 + oj];
#pragma unroll
        for (int i = 0; i < 4; i++) {
            u64 hh = *(const u64*)&Hs[(on + i) * 64 + k];
            fma2(acc[i][0], hh, w2.x);
            fma2(acc[i][1], hh, w2.y);
        }
    }
    float* m = bsel(msel);
#pragma unroll
    for (int i = 0; i < 4; i++) {
        int node = base + on + i;
        if (node < n_nodes) {
            float2 a0 = *(float2*)&acc[i][0];
            float2 a1 = *(float2*)&acc[i][1];
            *(float4*)(m + (size_t)node * 64 + oj) = make_float4(a0.x, a0.y, a1.x, a1.y);
        }
    }
}

// ---------------------------------------------------------------------------
// CSR gather: h[node] = sum over incoming edges of m[src]. NO atomics.
// 16 threads/node, float4 per thread.
// ---------------------------------------------------------------------------
__global__ void k_gather(int msel, int hsel, int n_nodes) {
    unsigned idx = blockIdx.x * blockDim.x + threadIdx.x;
    unsigned node = idx >> 4;
    unsigned c = idx & 15;
    if (node >= (unsigned)n_nodes) return;
    int s = g_off[node];
    int e = (node + 1 < (unsigned)n_nodes) ? g_off[node + 1] : N_EDGES;
    const float* m = bsel(msel);
    float4 acc = make_float4(0.f, 0.f, 0.f, 0.f);
    for (int j = s; j < e; j++) {
        int src = __ldg(&g_csr[j]);
        float4 v = *(const float4*)(m + (size_t)src * 64 + c * 4);
        acc.x += v.x; acc.y += v.y; acc.z += v.z; acc.w += v.w;
    }
    *(float4*)(bsel(hsel) + (size_t)node * 64 + c * 4) = acc;
}

// ---------------------------------------------------------------------------
// Layer-3 gather fused with mean-pool accumulation.
// ---------------------------------------------------------------------------
__global__ void k_gather_pool(int msel, const int* __restrict__ batch, int n_nodes) {
    unsigned idx = blockIdx.x * blockDim.x + threadIdx.x;
    unsigned node = idx >> 4;
    unsigned c = idx & 15;
    if (node >= (unsigned)n_nodes) return;
    int s = g_off[node];
    int e = (node + 1 < (unsigned)n_nodes) ? g_off[node + 1] : N_EDGES;
    const float* m = bsel(msel);
    float4 acc = make_float4(0.f, 0.f, 0.f, 0.f);
    for (int j = s; j < e; j++) {
        int src = __ldg(&g_csr[j]);
        float4 v = *(const float4*)(m + (size_t)src * 64 + c * 4);
        acc.x += v.x; acc.y += v.y; acc.z += v.z; acc.w += v.w;
    }
    int g = batch[node];
    float* p = g_sums + g * 64 + c * 4;
    asm volatile("red.global.add.v4.f32 [%0], {%1,%2,%3,%4};"
                 :: "l"(p), "f"(acc.x), "f"(acc.y), "f"(acc.z), "f"(acc.w) : "memory");
    if (c == 0) atomicAdd(&g_cnt[g], 1.0f);
}

// ---------------------------------------------------------------------------
// Final: out[g] = (sums[g]/max(cnt,1)) @ Wlin.
// ---------------------------------------------------------------------------
__global__ void k_final(const float* __restrict__ Wlin, float* __restrict__ out) {
    int idx = blockIdx.x * blockDim.x + threadIdx.x;
    if (idx >= N_GRAPHS * 16) return;
    int g = idx >> 4;
    int o = idx & 15;
    float inv = 1.0f / fmaxf(g_cnt[g], 1.0f);
    float acc = 0.f;
#pragma unroll
    for (int j = 0; j < 64; j++)
        acc = fmaf(g_sums[g * 64 + j], __ldg(Wlin + j * 16 + o), acc);
    out[idx] = acc * inv;
}

extern "C" void kernel_launch(void* const* d_in, const int* in_sizes, int n_in,
                              void* d_out, int out_size) {
    // Bind inputs BY ELEMENT COUNT (permutation-proof). W2/W3 (both 4096)
    // taken in order of appearance.
    const float *x = nullptr, *W1 = nullptr, *W2 = nullptr, *W3 = nullptr, *Wlin = nullptr;
    const int *ei = nullptr, *batch = nullptr;   // int32 (JAX x64-disabled)
    for (int i = 0; i < n_in; i++) {
        int s = in_sizes[i];
        const void* p = d_in[i];
        if (s == N_NODES * 128)      x = (const float*)p;
        else if (s == 128 * 64)      W1 = (const float*)p;
        else if (s == 64 * 64)       { if (!W2) W2 = (const float*)p; else W3 = (const float*)p; }
        else if (s == 64 * 16)       Wlin = (const float*)p;
        else if (s == 2 * N_EDGES)   ei = (const int*)p;
        else if (s == N_NODES)       batch = (const int*)p;
    }
    float* out = (float*)d_out;

    const int n_nodes = N_NODES;
    const int n_edges = N_EDGES;
    const int nblk_scan = (n_nodes + SCAN_BLK - 1) / SCAN_BLK;

    int gemm_blocks = (n_nodes + 63) / 64;
    int gath_blocks = (n_nodes * 16 + 255) / 256;
    int edge_blocks = (n_edges + 255) / 256;

    // CSR build (g_cur zero at entry: zero-init at load, re-zeroed by k_gemm1)
    k_count<<<edge_blocks, 256>>>(ei, n_edges);
    k_scan1<<<nblk_scan, 256>>>(n_nodes);
    k_scan3<<<nblk_scan, 256>>>(n_nodes, nblk_scan);
    k_fill<<<edge_blocks, 256>>>(ei, n_edges);

    // Layer 1: m1 = x@W1 -> buf0; h1 = gather(m1) -> buf1
    k_gemm1<<<gemm_blocks, 256>>>(x, W1, 0, n_nodes);
    k_gather<<<gath_blocks, 256>>>(0, 1, n_nodes);

    // Layer 2: m2 = relu(h1)@W2 -> buf0; h2 = gather(m2) -> buf1
    k_gemm_relu<<<gemm_blocks, 256>>>(1, W2, 0, n_nodes);
    k_gather<<<gath_blocks, 256>>>(0, 1, n_nodes);

    // Layer 3: m3 = relu(h2)@W3 -> buf0; gather fused with mean-pool
    k_gemm_relu<<<gemm_blocks, 256>>>(1, W3, 0, n_nodes);
    k_gather_pool<<<gath_blocks, 256>>>(0, batch, n_nodes);

    // Linear head
    k_final<<<(N_GRAPHS * 16 + 255) / 256, 256>>>(Wlin, out);
}

// round 15
// speedup vs baseline: 1.0829x; 1.0829x over previous
#include <cuda_runtime.h>
#include <cstdint>

#define N_NODES 100000
#define N_EDGES 1600000
#define N_GRAPHS 256
#define SCAN_BLK 1024   // elements per scan block

// Scratch (device globals; no allocation allowed). 2-buffer ping-pong.
__device__ __align__(256) float g_buf[2][N_NODES * 64];
__device__ __align__(256) float g_sums[N_GRAPHS * 64];
__device__ __align__(256) float g_cnt[N_GRAPHS];

// CSR scratch: edges grouped by destination node.
__device__ __align__(16) int g_off[N_NODES + 1];  // exclusive degree prefix
__device__ __align__(16) int g_cur[N_NODES];      // counts, then fill cursors
__device__ __align__(16) int g_csr[N_EDGES];      // src ids grouped by dst
__device__ int g_bsum[128];                       // spine of the scan

__device__ __forceinline__ float* bsel(int s) { return g_buf[s]; }

// ---------------------------------------------------------------------------
// Degree histogram over dst, 4 edges/thread (int4) for MLP. Also zeroes the
// pooling accumulators. g_cur is zero at entry (zero-init at load; re-zeroed
// by k_gemm1 each replay).
// ---------------------------------------------------------------------------
__global__ void k_count(const int* __restrict__ ei, int n_edges) {
    int i = blockIdx.x * blockDim.x + threadIdx.x;
    if (i < N_GRAPHS * 64) g_sums[i] = 0.f;
    if (i < N_GRAPHS) g_cnt[i] = 0.f;
    int q = n_edges >> 2;
    if (i < q) {
        int4 d = ((const int4*)(ei + n_edges))[i];
        atomicAdd(&g_cur[d.x], 1);
        atomicAdd(&g_cur[d.y], 1);
        atomicAdd(&g_cur[d.z], 1);
        atomicAdd(&g_cur[d.w], 1);
    }
}

// ---------------------------------------------------------------------------
// Scan pass 1: per-1024-element block exclusive scan of g_cur -> g_off,
// block totals -> g_bsum.
// ---------------------------------------------------------------------------
__global__ __launch_bounds__(256) void k_scan1(int n) {
    __shared__ int tsum[256];
    int t = threadIdx.x;
    int base = blockIdx.x * SCAN_BLK + t * 4;
    int v0 = (base + 0 < n) ? g_cur[base + 0] : 0;
    int v1 = (base + 1 < n) ? g_cur[base + 1] : 0;
    int v2 = (base + 2 < n) ? g_cur[base + 2] : 0;
    int v3 = (base + 3 < n) ? g_cur[base + 3] : 0;
    int s1 = v0 + v1, s2 = s1 + v2, s3 = s2 + v3;
    tsum[t] = s3;
    __syncthreads();
    for (int off = 1; off < 256; off <<= 1) {
        int x = (t >= off) ? tsum[t - off] : 0;
        __syncthreads();
        tsum[t] += x;
        __syncthreads();
    }
    int excl = (t > 0) ? tsum[t - 1] : 0;
    if (t == 255) g_bsum[blockIdx.x] = tsum[255];
    if (base + 0 < n) g_off[base + 0] = excl;
    if (base + 1 < n) g_off[base + 1] = excl + v0;
    if (base + 2 < n) g_off[base + 2] = excl + s1;
    if (base + 3 < n) g_off[base + 3] = excl + s2;
}

// ---------------------------------------------------------------------------
// Scan pass 2 (spine folded in): every block scans the <=128-entry spine
// locally, then applies its prefix. Final offsets -> g_off, cursors -> g_cur.
// ---------------------------------------------------------------------------
__global__ __launch_bounds__(256) void k_scan3(int n, int nblk) {
    __shared__ int sp[128];
    int t = threadIdx.x;
    if (t < 128) sp[t] = (t < nblk) ? g_bsum[t] : 0;
    __syncthreads();
    for (int off = 1; off < 128; off <<= 1) {
        int x = (t < 128 && t >= off) ? sp[t - off] : 0;
        __syncthreads();
        if (t < 128) sp[t] += x;
        __syncthreads();
    }
    int b = blockIdx.x;
    int spine = (b > 0) ? sp[b - 1] : 0;
#pragma unroll
    for (int r = 0; r < 4; r++) {
        int i = b * SCAN_BLK + r * 256 + t;
        if (i < n) {
            int o = g_off[i] + spine;
            g_off[i] = o;
            g_cur[i] = o;
        }
    }
    if (b == 0 && t == 0) g_off[n] = N_EDGES;
}

// ---------------------------------------------------------------------------
// Fill CSR: group src ids by dst. 4 edges/thread (int4) for MLP.
// ---------------------------------------------------------------------------
__global__ void k_fill(const int* __restrict__ ei, int n_edges) {
    int i = blockIdx.x * blockDim.x + threadIdx.x;
    int q = n_edges >> 2;
    if (i >= q) return;
    int4 s = ((const int4*)ei)[i];
    int4 d = ((const int4*)(ei + n_edges))[i];
    g_csr[atomicAdd(&g_cur[d.x], 1)] = s.x;
    g_csr[atomicAdd(&g_cur[d.y], 1)] = s.y;
    g_csr[atomicAdd(&g_cur[d.z], 1)] = s.z;
    g_csr[atomicAdd(&g_cur[d.w], 1)] = s.w;
}

// ---------------------------------------------------------------------------
// Layer-1 GEMM: m = x @ W1 (K=128). 64x64 tile, 4x4 register tile/thread.
// Ws (32KB) staged once; Hs re-staged per 64-K chunk. 48KB static smem.
// Also re-zeroes g_cur for the next replay (runs after k_fill).
// ---------------------------------------------------------------------------
__global__ __launch_bounds__(256) void k_gemm1(const float* __restrict__ x,
                                               const float* __restrict__ W,
                                               int msel, int n_nodes) {
    __shared__ float Ws[128 * 64];
    __shared__ float Hs[64 * 64];
    int t = threadIdx.x;
    int base = blockIdx.x * 64;

    if (t < 64 && base + t < n_nodes) g_cur[base + t] = 0;

    for (int i = t; i < 128 * 16; i += 256)
        ((float4*)Ws)[i] = ((const float4*)W)[i];

    int oj = (t & 15) * 4;
    int on = (t >> 4) * 4;
    float acc[4][4] = {};
#pragma unroll
    for (int kc = 0; kc < 2; kc++) {
        __syncthreads();
        for (int i = t; i < 64 * 16; i += 256) {
            int n = i >> 4, c = i & 15;
            int node = base + n;
            float4 v = make_float4(0.f, 0.f, 0.f, 0.f);
            if (node < n_nodes)
                v = ((const float4*)(x + (size_t)node * 128 + kc * 64))[c];
            ((float4*)Hs)[i] = v;
        }
        __syncthreads();
#pragma unroll 8
        for (int k = 0; k < 64; k++) {
            float4 w = *(const float4*)&Ws[(kc * 64 + k) * 64 + oj];
#pragma unroll
            for (int i = 0; i < 4; i++) {
                float h = Hs[(on + i) * 64 + k];
                acc[i][0] = fmaf(h, w.x, acc[i][0]);
                acc[i][1] = fmaf(h, w.y, acc[i][1]);
                acc[i][2] = fmaf(h, w.z, acc[i][2]);
                acc[i][3] = fmaf(h, w.w, acc[i][3]);
            }
        }
    }
    float* m = bsel(msel);
#pragma unroll
    for (int i = 0; i < 4; i++) {
        int node = base + on + i;
        if (node < n_nodes)
            *(float4*)(m + (size_t)node * 64 + oj) =
                make_float4(acc[i][0], acc[i][1], acc[i][2], acc[i][3]);
    }
}

// ---------------------------------------------------------------------------
// Layers 2/3 GEMM: m = relu(h_in) @ W (K=64). Relu applied at staging.
// ---------------------------------------------------------------------------
__global__ __launch_bounds__(256) void k_gemm_relu(int insel, const float* __restrict__ W,
                                                   int msel, int n_nodes) {
    __shared__ float Ws[64 * 64];
    __shared__ float Hs[64 * 64];
    int t = threadIdx.x;
    const float* src = bsel(insel);
    int base = blockIdx.x * 64;
    for (int i = t; i < 64 * 16; i += 256)
        ((float4*)Ws)[i] = ((const float4*)W)[i];
    for (int i = t; i < 64 * 16; i += 256) {
        int n = i >> 4, c = i & 15;
        int node = base + n;
        float4 v = make_float4(0.f, 0.f, 0.f, 0.f);
        if (node < n_nodes) v = ((const float4*)(src + (size_t)node * 64))[c];
        v.x = fmaxf(v.x, 0.f); v.y = fmaxf(v.y, 0.f);
        v.z = fmaxf(v.z, 0.f); v.w = fmaxf(v.w, 0.f);
        ((float4*)Hs)[i] = v;
    }
    __syncthreads();

    int oj = (t & 15) * 4;
    int on = (t >> 4) * 4;
    float acc[4][4] = {};
#pragma unroll 8
    for (int k = 0; k < 64; k++) {
        float4 w = *(const float4*)&Ws[k * 64 + oj];
#pragma unroll
        for (int i = 0; i < 4; i++) {
            float h = Hs[(on + i) * 64 + k];
            acc[i][0] = fmaf(h, w.x, acc[i][0]);
            acc[i][1] = fmaf(h, w.y, acc[i][1]);
            acc[i][2] = fmaf(h, w.z, acc[i][2]);
            acc[i][3] = fmaf(h, w.w, acc[i][3]);
        }
    }
    float* m = bsel(msel);
#pragma unroll
    for (int i = 0; i < 4; i++) {
        int node = base + on + i;
        if (node < n_nodes)
            *(float4*)(m + (size_t)node * 64 + oj) =
                make_float4(acc[i][0], acc[i][1], acc[i][2], acc[i][3]);
    }
}

// ---------------------------------------------------------------------------
// CSR gather: h[node] = sum over incoming edges of m[src]. NO atomics.
// 16 threads/node, float4 per thread.
// ---------------------------------------------------------------------------
__global__ void k_gather(int msel, int hsel, int n_nodes) {
    unsigned idx = blockIdx.x * blockDim.x + threadIdx.x;
    unsigned node = idx >> 4;
    unsigned c = idx & 15;
    if (node >= (unsigned)n_nodes) return;
    int s = g_off[node];
    int e = g_off[node + 1];
    const float* m = bsel(msel);
    float4 acc = make_float4(0.f, 0.f, 0.f, 0.f);
    for (int j = s; j < e; j++) {
        int src = __ldg(&g_csr[j]);
        float4 v = *(const float4*)(m + (size_t)src * 64 + c * 4);
        acc.x += v.x; acc.y += v.y; acc.z += v.z; acc.w += v.w;
    }
    *(float4*)(bsel(hsel) + (size_t)node * 64 + c * 4) = acc;
}

// ---------------------------------------------------------------------------
// Layer-3 gather fused with mean-pool accumulation.
// ---------------------------------------------------------------------------
__global__ void k_gather_pool(int msel, const int* __restrict__ batch, int n_nodes) {
    unsigned idx = blockIdx.x * blockDim.x + threadIdx.x;
    unsigned node = idx >> 4;
    unsigned c = idx & 15;
    if (node >= (unsigned)n_nodes) return;
    int s = g_off[node];
    int e = g_off[node + 1];
    const float* m = bsel(msel);
    float4 acc = make_float4(0.f, 0.f, 0.f, 0.f);
    for (int j = s; j < e; j++) {
        int src = __ldg(&g_csr[j]);
        float4 v = *(const float4*)(m + (size_t)src * 64 + c * 4);
        acc.x += v.x; acc.y += v.y; acc.z += v.z; acc.w += v.w;
    }
    int g = batch[node];
    float* p = g_sums + g * 64 + c * 4;
    asm volatile("red.global.add.v4.f32 [%0], {%1,%2,%3,%4};"
                 :: "l"(p), "f"(acc.x), "f"(acc.y), "f"(acc.z), "f"(acc.w) : "memory");
    if (c == 0) atomicAdd(&g_cnt[g], 1.0f);
}

// ---------------------------------------------------------------------------
// Final: out[g] = (sums[g]/max(cnt,1)) @ Wlin.
// ---------------------------------------------------------------------------
__global__ void k_final(const float* __restrict__ Wlin, float* __restrict__ out) {
    int idx = blockIdx.x * blockDim.x + threadIdx.x;
    if (idx >= N_GRAPHS * 16) return;
    int g = idx >> 4;
    int o = idx & 15;
    float inv = 1.0f / fmaxf(g_cnt[g], 1.0f);
    float acc = 0.f;
#pragma unroll
    for (int j = 0; j < 64; j++)
        acc = fmaf(g_sums[g * 64 + j], __ldg(Wlin + j * 16 + o), acc);
    out[idx] = acc * inv;
}

extern "C" void kernel_launch(void* const* d_in, const int* in_sizes, int n_in,
                              void* d_out, int out_size) {
    // Bind inputs BY ELEMENT COUNT (permutation-proof). W2/W3 (both 4096)
    // taken in order of appearance.
    const float *x = nullptr, *W1 = nullptr, *W2 = nullptr, *W3 = nullptr, *Wlin = nullptr;
    const int *ei = nullptr, *batch = nullptr;   // int32 (JAX x64-disabled)
    for (int i = 0; i < n_in; i++) {
        int s = in_sizes[i];
        const void* p = d_in[i];
        if (s == N_NODES * 128)      x = (const float*)p;
        else if (s == 128 * 64)      W1 = (const float*)p;
        else if (s == 64 * 64)       { if (!W2) W2 = (const float*)p; else W3 = (const float*)p; }
        else if (s == 64 * 16)       Wlin = (const float*)p;
        else if (s == 2 * N_EDGES)   ei = (const int*)p;
        else if (s == N_NODES)       batch = (const int*)p;
    }
    float* out = (float*)d_out;

    const int n_nodes = N_NODES;
    const int n_edges = N_EDGES;
    const int nblk_scan = (n_nodes + SCAN_BLK - 1) / SCAN_BLK;

    int gemm_blocks = (n_nodes + 63) / 64;
    int gath_blocks = (n_nodes * 16 + 255) / 256;
    int eq_blocks = ((n_edges >> 2) + 255) / 256;

    // CSR build (g_cur zero at entry: zero-init at load, re-zeroed by k_gemm1)
    k_count<<<eq_blocks, 256>>>(ei, n_edges);
    k_scan1<<<nblk_scan, 256>>>(n_nodes);
    k_scan3<<<nblk_scan, 256>>>(n_nodes, nblk_scan);
    k_fill<<<eq_blocks, 256>>>(ei, n_edges);

    // Layer 1: m1 = x@W1 -> buf0; h1 = gather(m1) -> buf1
    k_gemm1<<<gemm_blocks, 256>>>(x, W1, 0, n_nodes);
    k_gather<<<gath_blocks, 256>>>(0, 1, n_nodes);

    // Layer 2: m2 = relu(h1)@W2 -> buf0; h2 = gather(m2) -> buf1
    k_gemm_relu<<<gemm_blocks, 256>>>(1, W2, 0, n_nodes);
    k_gather<<<gath_blocks, 256>>>(0, 1, n_nodes);

    // Layer 3: m3 = relu(h2)@W3 -> buf0; gather fused with mean-pool
    k_gemm_relu<<<gemm_blocks, 256>>>(1, W3, 0, n_nodes);
    k_gather_pool<<<gath_blocks, 256>>>(0, batch, n_nodes);

    // Linear head
    k_final<<<(N_GRAPHS * 16 + 255) / 256, 256>>>(Wlin, out);
}